// round 13
// baseline (speedup 1.0000x reference)
#include <cuda_runtime.h>
#include <cuda_fp16.h>
#include <cstdint>

// KohonenMap: 3xFP16-split mma.sync (hh+hl+lh) top-2 pass + exact fp32 refine.
// R12: replace mbarrier handshakes (TRYWAIT=90cyc fast-path) with
// cp.async.wait_group + __syncthreads (7-47cyc), incremental producer pointers.
#define NPTS 65536
#define KNEU 4096
#define DDIM 512
#define BM 64
#define BN 128
#define NTH 256
#define NST 3
#define NCHUNK (KNEU / BN)    // 32
#define NSTEP  (DDIM / 32)    // 16 BK-32 steps per chunk
#define TOTSTEP (NCHUNK * NSTEP)   // 512
#define MARGIN_TH 0.05f

__device__ __half g_xh[(size_t)NPTS * DDIM];
__device__ __half g_xl[(size_t)NPTS * DDIM];
__device__ __half g_wh[(size_t)KNEU * DDIM];
__device__ __half g_wl[(size_t)KNEU * DDIM];
__device__ float  g_w2[KNEU];

// stage (BK=32, 80B-padded rows; 64B data per row):
//   Ah[64x80] Al[64x80] Bh[128x80] Bl[128x80] = 30720 B
#define SROW 80
#define STG_AH 0
#define STG_AL 5120
#define STG_BH 10240
#define STG_BL 20480
#define STG_BYTES 30720
#define SMEM_DYN (NST * STG_BYTES)   // 92160 -> 2 CTAs/SM

extern __shared__ char dynsmem[];

__device__ __forceinline__ uint32_t smem_u32(const void* p) {
    uint32_t a;
    asm("{ .reg .u64 t; cvta.to.shared.u64 t, %1; cvt.u32.u64 %0, t; }" : "=r"(a) : "l"(p));
    return a;
}
__device__ __forceinline__ void cp16(uint32_t dst, const void* src) {
    asm volatile("cp.async.cg.shared.global [%0], [%1], 16;" :: "r"(dst), "l"(src));
}
#define CP_COMMIT() asm volatile("cp.async.commit_group;")
#define CP_WAIT1()  asm volatile("cp.async.wait_group 1;")

__device__ __forceinline__ void ldm_x4(uint32_t* r, uint32_t addr) {
    asm volatile("ldmatrix.sync.aligned.m8n8.x4.shared.b16 {%0,%1,%2,%3}, [%4];"
        : "=r"(r[0]), "=r"(r[1]), "=r"(r[2]), "=r"(r[3]) : "r"(addr));
}

__device__ __forceinline__ void mma16816(float* c, const uint32_t* a, const uint32_t* b) {
    asm volatile(
        "mma.sync.aligned.m16n8k16.row.col.f32.f16.f16.f32 "
        "{%0,%1,%2,%3}, {%4,%5,%6,%7}, {%8,%9}, {%0,%1,%2,%3};"
        : "+f"(c[0]), "+f"(c[1]), "+f"(c[2]), "+f"(c[3])
        : "r"(a[0]), "r"(a[1]), "r"(a[2]), "r"(a[3]), "r"(b[0]), "r"(b[1]));
}

__device__ __forceinline__ void top2_upd(float d, int idx, float& v1, int& i1,
                                         float& v2, int& i2) {
    if (d < v1 || (d == v1 && idx < i1)) { v2 = v1; i2 = i1; v1 = d; i1 = idx; }
    else if (d < v2 || (d == v2 && idx < i2)) { v2 = d; i2 = idx; }
}

// ---------------- prep kernels ----------------
__global__ void prep16(const float* __restrict__ s, __half* __restrict__ dh,
                       __half* __restrict__ dl) {
    size_t i = (size_t)blockIdx.x * blockDim.x + threadIdx.x;
    float4 v = reinterpret_cast<const float4*>(s)[i];
    __half hx = __float2half_rn(v.x), hy = __float2half_rn(v.y);
    __half hz = __float2half_rn(v.z), hw = __float2half_rn(v.w);
    __half lx = __float2half_rn(v.x - __half2float(hx));
    __half ly = __float2half_rn(v.y - __half2float(hy));
    __half lz = __float2half_rn(v.z - __half2float(hz));
    __half lw = __float2half_rn(v.w - __half2float(hw));
    __half2 h01 = __halves2half2(hx, hy), h23 = __halves2half2(hz, hw);
    __half2 l01 = __halves2half2(lx, ly), l23 = __halves2half2(lz, lw);
    uint2 ph, pl;
    ph.x = *reinterpret_cast<uint32_t*>(&h01); ph.y = *reinterpret_cast<uint32_t*>(&h23);
    pl.x = *reinterpret_cast<uint32_t*>(&l01); pl.y = *reinterpret_cast<uint32_t*>(&l23);
    reinterpret_cast<uint2*>(dh)[i] = ph;
    reinterpret_cast<uint2*>(dl)[i] = pl;
}

__global__ void w2_kernel(const float* __restrict__ w) {
    int warp = (blockIdx.x * blockDim.x + threadIdx.x) >> 5;
    int lane = threadIdx.x & 31;
    if (warp >= KNEU) return;
    const float4* row = reinterpret_cast<const float4*>(w + (size_t)warp * DDIM);
    float s = 0.f;
#pragma unroll
    for (int i = 0; i < DDIM / 128; ++i) {
        float4 v = row[lane + i * 32];
        s += v.x * v.x + v.y * v.y + v.z * v.z + v.w * v.w;
    }
#pragma unroll
    for (int off = 16; off > 0; off >>= 1) s += __shfl_xor_sync(0xffffffff, s, off);
    if (lane == 0) g_w2[warp] = s;
}

// ---------------- main kernel ----------------
__global__ void __launch_bounds__(NTH, 2)
som_mma(const float* __restrict__ x, const float* __restrict__ w,
        float* __restrict__ out) {
    __shared__ float s_v1[BM][4], s_v2[BM][4];
    __shared__ int   s_i1[BM][4], s_i2[BM][4];
    __shared__ int   s_bmu[BM];

    const int tid = threadIdx.x;
    const int wid = tid >> 5;
    const int lane = tid & 31;
    const int g4 = lane >> 2;
    const int tig = lane & 3;
    const int warpM = wid & 1;        // 2 M-warps, 32 rows each
    const int warpN = wid >> 1;       // 4 N-warps, 32 cols each
    const int rowBase = blockIdx.x * BM;
    const uint32_t sb = smem_u32(dynsmem);
    const uint32_t sbEnd = sb + NST * STG_BYTES;

    // ldmatrix lane decomposition (proven mapping R7-R11)
    const int lr = lane & 15;
    const int lh = lane >> 4;
    const int bt = lane >> 3;
    const int br = lane & 7;
    const int b_noff = ((bt >> 1) << 3) + br;
    const int b_koff = (bt & 1) << 4;

    // producer mapping: 6 cp16/thread/stage
    const int bR = tid >> 1;              // B row 0..127
    const int bQ = (tid & 1) * 2;         // B quarters bQ, bQ+1
    const int aR = tid >> 2;              // A row 0..63
    const int aQ = tid & 3;               // A quarter
    const uint32_t bOff = (uint32_t)(bR * SROW + bQ * 16);
    const uint32_t aOff = (uint32_t)(aR * SROW + aQ * 16);

    // incremental producer pointers (advance +32 elems/step)
    const __half* pwh = g_wh + (size_t)bR * DDIM + bQ * 8;
    const __half* pwl = g_wl + (size_t)bR * DDIM + bQ * 8;
    const __half* pxh = g_xh + (size_t)(rowBase + aR) * DDIM + aQ * 8;
    const __half* pxl = g_xl + (size_t)(rowBase + aR) * DDIM + aQ * 8;

    // prologue: fill stages 0,1 (producer steps 0,1 of chunk 0)
#pragma unroll
    for (int p = 0; p < NST - 1; ++p) {
        const uint32_t stg = sb + p * STG_BYTES;
        cp16(stg + STG_BH + bOff,      pwh);
        cp16(stg + STG_BH + bOff + 16, pwh + 8);
        cp16(stg + STG_BL + bOff,      pwl);
        cp16(stg + STG_BL + bOff + 16, pwl + 8);
        cp16(stg + STG_AH + aOff,      pxh);
        cp16(stg + STG_AL + aOff,      pxl);
        CP_COMMIT();
        pwh += 32; pwl += 32; pxh += 32; pxl += 32;
    }
    int pc = NST - 1;               // producer step within its chunk (0..15)
    int prodLeft = TOTSTEP - (NST - 1);
    uint32_t pstg = sb + (NST - 1) * STG_BYTES;   // stage to fill next
    uint32_t cstg = sb;                            // stage to consume next

    // running top-2 per owned sub-row
    float rv1[2][2], rv2[2][2];
    int   ri1[2][2], ri2[2][2];
#pragma unroll
    for (int a = 0; a < 2; ++a)
#pragma unroll
        for (int b = 0; b < 2; ++b) {
            rv1[a][b] = 3.4e38f; rv2[a][b] = 3.4e38f;
            ri1[a][b] = 0x7fffffff; ri2[a][b] = 0x7fffffff;
        }

    for (int ch = 0; ch < NCHUNK; ++ch) {
        float2 w2r[4];
#pragma unroll
        for (int nt = 0; nt < 4; ++nt)
            w2r[nt] = *reinterpret_cast<const float2*>(
                &g_w2[ch * BN + warpN * 32 + nt * 8 + tig * 2]);

        float acc[2][4][4];
#pragma unroll
        for (int mt = 0; mt < 2; ++mt)
#pragma unroll
            for (int nt = 0; nt < 4; ++nt)
#pragma unroll
                for (int i = 0; i < 4; ++i) acc[mt][nt][i] = 0.f;

        for (int s = 0; s < NSTEP; ++s) {
            // stage cstg's cp.async group complete (own), then globally visible
            CP_WAIT1();
            __syncthreads();

            // ---- produce stage gs+2 (overwrites stage consumed in gs-1; safe
            // because the barrier above ordered all warps past step gs-1) ----
            if (prodLeft > 0) {
                --prodLeft;
                cp16(pstg + STG_BH + bOff,      pwh);
                cp16(pstg + STG_BH + bOff + 16, pwh + 8);
                cp16(pstg + STG_BL + bOff,      pwl);
                cp16(pstg + STG_BL + bOff + 16, pwl + 8);
                cp16(pstg + STG_AH + aOff,      pxh);
                cp16(pstg + STG_AL + aOff,      pxl);
                pwh += 32; pwl += 32; pxh += 32; pxl += 32;
                if (++pc == NSTEP) {            // producer crosses chunk boundary
                    pc = 0;
                    pwh += (size_t)(BN - 1) * DDIM;
                    pwl += (size_t)(BN - 1) * DDIM;
                    pxh -= DDIM;
                    pxl -= DDIM;
                }
                pstg += STG_BYTES;
                if (pstg == sbEnd) pstg = sb;
            }
            CP_COMMIT();

            // ---- consume stage cstg: two k16 sub-rounds ----
#pragma unroll
            for (int sub = 0; sub < 2; ++sub) {
                const int so = sub * 32;
                uint32_t ah[2][4], al[2][4], bh[4][2], bl[4][2];

                uint32_t aaddr = cstg + STG_AH + (warpM * 32 + lr) * SROW + lh * 16 + so;
                ldm_x4(ah[0], aaddr);
                ldm_x4(ah[1], aaddr + 16 * SROW);
                uint32_t aladdr = cstg + STG_AL + (warpM * 32 + lr) * SROW + lh * 16 + so;
                ldm_x4(al[0], aladdr);
                ldm_x4(al[1], aladdr + 16 * SROW);
                uint32_t bhaddr = cstg + STG_BH + (warpN * 32 + b_noff) * SROW + b_koff + so;
                ldm_x4(&bh[0][0], bhaddr);
                ldm_x4(&bh[2][0], bhaddr + 16 * SROW);
                uint32_t bladdr = cstg + STG_BL + (warpN * 32 + b_noff) * SROW + b_koff + so;
                ldm_x4(&bl[0][0], bladdr);
                ldm_x4(&bl[2][0], bladdr + 16 * SROW);

#pragma unroll
                for (int mt = 0; mt < 2; ++mt)
#pragma unroll
                    for (int nt = 0; nt < 4; ++nt)
                        mma16816(acc[mt][nt], ah[mt], bh[nt]);   // hi*hi
#pragma unroll
                for (int mt = 0; mt < 2; ++mt)
#pragma unroll
                    for (int nt = 0; nt < 4; ++nt)
                        mma16816(acc[mt][nt], ah[mt], bl[nt]);   // hi*lo
#pragma unroll
                for (int mt = 0; mt < 2; ++mt)
#pragma unroll
                    for (int nt = 0; nt < 4; ++nt)
                        mma16816(acc[mt][nt], al[mt], bh[nt]);   // lo*hi
            }
            cstg += STG_BYTES;
            if (cstg == sbEnd) cstg = sb;
        }

        // epilogue: per-chunk local top-2, butterfly over 4 threads, merge
        const int idxBase = ch * BN + warpN * 32 + tig * 2;
#pragma unroll
        for (int mt = 0; mt < 2; ++mt) {
#pragma unroll
            for (int r2 = 0; r2 < 2; ++r2) {
                float lv1 = 3.4e38f, lv2 = 3.4e38f;
                int li1 = 0x7fffffff, li2 = 0x7fffffff;
#pragma unroll
                for (int nt = 0; nt < 4; ++nt) {
#pragma unroll
                    for (int c2 = 0; c2 < 2; ++c2) {
                        float dot = acc[mt][nt][r2 * 2 + c2];
                        float w2v = c2 ? w2r[nt].y : w2r[nt].x;
                        float dist = fmaf(-2.f, dot, w2v);
                        top2_upd(dist, idxBase + nt * 8 + c2, lv1, li1, lv2, li2);
                    }
                }
#pragma unroll
                for (int off = 1; off < 4; off <<= 1) {
                    float o1 = __shfl_xor_sync(0xffffffffu, lv1, off);
                    int   p1 = __shfl_xor_sync(0xffffffffu, li1, off);
                    float o2 = __shfl_xor_sync(0xffffffffu, lv2, off);
                    int   p2 = __shfl_xor_sync(0xffffffffu, li2, off);
                    top2_upd(o1, p1, lv1, li1, lv2, li2);
                    top2_upd(o2, p2, lv1, li1, lv2, li2);
                }
                top2_upd(lv1, li1, rv1[mt][r2], ri1[mt][r2], rv2[mt][r2], ri2[mt][r2]);
                top2_upd(lv2, li2, rv1[mt][r2], ri1[mt][r2], rv2[mt][r2], ri2[mt][r2]);
            }
        }
    }

    // cross-warp merge + margin test + exact refine
    if (tig == 0) {
#pragma unroll
        for (int mt = 0; mt < 2; ++mt)
#pragma unroll
            for (int r2 = 0; r2 < 2; ++r2) {
                int row = warpM * 32 + mt * 16 + g4 + r2 * 8;
                s_v1[row][warpN] = rv1[mt][r2]; s_i1[row][warpN] = ri1[mt][r2];
                s_v2[row][warpN] = rv2[mt][r2]; s_i2[row][warpN] = ri2[mt][r2];
            }
    }
    __syncthreads();
    if (tid < BM) {
        float v1 = s_v1[tid][0], v2 = s_v2[tid][0];
        int   i1 = s_i1[tid][0], i2 = s_i2[tid][0];
#pragma unroll
        for (int wn = 1; wn < 4; ++wn) {
            top2_upd(s_v1[tid][wn], s_i1[tid][wn], v1, i1, v2, i2);
            top2_upd(s_v2[tid][wn], s_i2[tid][wn], v1, i1, v2, i2);
        }
        int bmu = i1;
        if (v2 - v1 < MARGIN_TH) {
            // exact fp32 refine: identical FMA chain to the validated r1 kernel
            const float* xr = x + (size_t)(rowBase + tid) * DDIM;
            const float* w1p = w + (size_t)i1 * DDIM;
            const float* w2p = w + (size_t)i2 * DDIM;
            float a1 = 0.f, a2 = 0.f;
#pragma unroll 8
            for (int k = 0; k < DDIM; ++k) {
                float xv = xr[k];
                a1 = fmaf(xv, w1p[k], a1);
                a2 = fmaf(xv, w2p[k], a2);
            }
            float d1 = fmaf(-2.f, a1, g_w2[i1]);
            float d2 = fmaf(-2.f, a2, g_w2[i2]);
            if (d2 < d1 || (d2 == d1 && i2 < i1)) bmu = i2;
        }
        s_bmu[tid] = bmu;
    }
    __syncthreads();

    for (int t = tid; t < BM * (DDIM / 4); t += NTH) {
        int r = t >> 7;
        int cc = t & 127;
        reinterpret_cast<float4*>(out + (size_t)(rowBase + r) * DDIM)[cc] =
            reinterpret_cast<const float4*>(w + (size_t)s_bmu[r] * DDIM)[cc];
    }
}

// ---------------- launch ----------------
extern "C" void kernel_launch(void* const* d_in, const int* in_sizes, int n_in,
                              void* d_out, int out_size) {
    const float* x = (const float*)d_in[0];
    const float* w = (const float*)d_in[1];
    float* out = (float*)d_out;

    __half *xh, *xl, *wh, *wl;
    cudaGetSymbolAddress((void**)&xh, g_xh);
    cudaGetSymbolAddress((void**)&xl, g_xl);
    cudaGetSymbolAddress((void**)&wh, g_wh);
    cudaGetSymbolAddress((void**)&wl, g_wl);

    prep16<<<(NPTS * DDIM / 4) / 256, 256>>>(x, xh, xl);
    prep16<<<(KNEU * DDIM / 4) / 256, 256>>>(w, wh, wl);
    w2_kernel<<<KNEU / 8, 256>>>(w);

    cudaFuncSetAttribute(som_mma, cudaFuncAttributeMaxDynamicSharedMemorySize, SMEM_DYN);
    som_mma<<<NPTS / BM, NTH, SMEM_DYN>>>(x, w, out);
}

// round 14
// speedup vs baseline: 1.3416x; 1.3416x over previous
#include <cuda_runtime.h>
#include <cuda_fp16.h>
#include <cstdint>

// KohonenMap: 3xFP16-split mma.sync (hh+hl+lh) top-2 pass + exact fp32 refine.
// R14: R11 pipeline (best: mbarriers, sync AFTER MMA issue) + R12's incremental
// producer pointers (cut alu 19.5% -> ~12%). R13 proved top-of-step barriers
// realign LDSM bursts and starve the tensor pipe; reverted.
#define NPTS 65536
#define KNEU 4096
#define DDIM 512
#define BM 64
#define BN 128
#define NTH 256
#define NST 3
#define NCHUNK (KNEU / BN)    // 32
#define NSTEP  (DDIM / 32)    // 16 BK-32 steps per chunk
#define TOTSTEP (NCHUNK * NSTEP)   // 512
#define MARGIN_TH 0.05f

__device__ __half g_xh[(size_t)NPTS * DDIM];
__device__ __half g_xl[(size_t)NPTS * DDIM];
__device__ __half g_wh[(size_t)KNEU * DDIM];
__device__ __half g_wl[(size_t)KNEU * DDIM];
__device__ float  g_w2[KNEU];

// stage (BK=32, 80B-padded rows; 64B data per row):
//   Ah[64x80] Al[64x80] Bh[128x80] Bl[128x80] = 30720 B
#define SROW 80
#define STG_AH 0
#define STG_AL 5120
#define STG_BH 10240
#define STG_BL 20480
#define STG_BYTES 30720
#define SMEM_DYN (NST * STG_BYTES)   // 92160 -> 2 CTAs/SM

extern __shared__ char dynsmem[];

__device__ __forceinline__ uint32_t smem_u32(const void* p) {
    uint32_t a;
    asm("{ .reg .u64 t; cvta.to.shared.u64 t, %1; cvt.u32.u64 %0, t; }" : "=r"(a) : "l"(p));
    return a;
}
__device__ __forceinline__ void cp16(uint32_t dst, const void* src) {
    asm volatile("cp.async.cg.shared.global [%0], [%1], 16;" :: "r"(dst), "l"(src));
}

#define MBAR_INIT(mb, c) \
    asm volatile("mbarrier.init.shared.b64 [%0], %1;" :: "r"(mb), "r"(c) : "memory")
#define MBAR_ARRIVE(mb) \
    asm volatile("mbarrier.arrive.shared.b64 _, [%0];" :: "r"(mb) : "memory")
#define CPASYNC_MBAR_ARRIVE(mb) \
    asm volatile("cp.async.mbarrier.arrive.noinc.shared.b64 [%0];" :: "r"(mb) : "memory")

#define MBAR_WAIT_PARITY(mbar_addr, par) do {                                            \
    uint32_t _mb = (uint32_t)(mbar_addr); uint32_t _p = (uint32_t)(par); uint32_t _done; \
    asm volatile("{ .reg .pred p; mbarrier.try_wait.parity.acquire.cta.shared::cta.b64 " \
                 "p, [%1], %2; selp.b32 %0,1,0,p; }"                                     \
                 : "=r"(_done) : "r"(_mb), "r"(_p) : "memory");                          \
    if (!_done) {                                                                        \
        asm volatile("{ .reg .pred P1; WL_%=: "                                          \
            "mbarrier.try_wait.parity.acquire.cta.shared::cta.b64 P1, [%0], %1, 0x989680;"\
            " @P1 bra.uni WD_%=; bra.uni WL_%=; WD_%=: }"                                \
            :: "r"(_mb), "r"(_p) : "memory");                                            \
    }                                                                                    \
} while (0)

__device__ __forceinline__ void ldm_x4(uint32_t* r, uint32_t addr) {
    asm volatile("ldmatrix.sync.aligned.m8n8.x4.shared.b16 {%0,%1,%2,%3}, [%4];"
        : "=r"(r[0]), "=r"(r[1]), "=r"(r[2]), "=r"(r[3]) : "r"(addr));
}

__device__ __forceinline__ void mma16816(float* c, const uint32_t* a, const uint32_t* b) {
    asm volatile(
        "mma.sync.aligned.m16n8k16.row.col.f32.f16.f16.f32 "
        "{%0,%1,%2,%3}, {%4,%5,%6,%7}, {%8,%9}, {%0,%1,%2,%3};"
        : "+f"(c[0]), "+f"(c[1]), "+f"(c[2]), "+f"(c[3])
        : "r"(a[0]), "r"(a[1]), "r"(a[2]), "r"(a[3]), "r"(b[0]), "r"(b[1]));
}

__device__ __forceinline__ void top2_upd(float d, int idx, float& v1, int& i1,
                                         float& v2, int& i2) {
    if (d < v1 || (d == v1 && idx < i1)) { v2 = v1; i2 = i1; v1 = d; i1 = idx; }
    else if (d < v2 || (d == v2 && idx < i2)) { v2 = d; i2 = idx; }
}

// ---------------- prep kernels ----------------
__global__ void prep16(const float* __restrict__ s, __half* __restrict__ dh,
                       __half* __restrict__ dl) {
    size_t i = (size_t)blockIdx.x * blockDim.x + threadIdx.x;
    float4 v = reinterpret_cast<const float4*>(s)[i];
    __half hx = __float2half_rn(v.x), hy = __float2half_rn(v.y);
    __half hz = __float2half_rn(v.z), hw = __float2half_rn(v.w);
    __half lx = __float2half_rn(v.x - __half2float(hx));
    __half ly = __float2half_rn(v.y - __half2float(hy));
    __half lz = __float2half_rn(v.z - __half2float(hz));
    __half lw = __float2half_rn(v.w - __half2float(hw));
    __half2 h01 = __halves2half2(hx, hy), h23 = __halves2half2(hz, hw);
    __half2 l01 = __halves2half2(lx, ly), l23 = __halves2half2(lz, lw);
    uint2 ph, pl;
    ph.x = *reinterpret_cast<uint32_t*>(&h01); ph.y = *reinterpret_cast<uint32_t*>(&h23);
    pl.x = *reinterpret_cast<uint32_t*>(&l01); pl.y = *reinterpret_cast<uint32_t*>(&l23);
    reinterpret_cast<uint2*>(dh)[i] = ph;
    reinterpret_cast<uint2*>(dl)[i] = pl;
}

__global__ void w2_kernel(const float* __restrict__ w) {
    int warp = (blockIdx.x * blockDim.x + threadIdx.x) >> 5;
    int lane = threadIdx.x & 31;
    if (warp >= KNEU) return;
    const float4* row = reinterpret_cast<const float4*>(w + (size_t)warp * DDIM);
    float s = 0.f;
#pragma unroll
    for (int i = 0; i < DDIM / 128; ++i) {
        float4 v = row[lane + i * 32];
        s += v.x * v.x + v.y * v.y + v.z * v.z + v.w * v.w;
    }
#pragma unroll
    for (int off = 16; off > 0; off >>= 1) s += __shfl_xor_sync(0xffffffff, s, off);
    if (lane == 0) g_w2[warp] = s;
}

// ---------------- main kernel ----------------
__global__ void __launch_bounds__(NTH, 2)
som_mma(const float* __restrict__ x, const float* __restrict__ w,
        float* __restrict__ out) {
    __shared__ __align__(8) uint64_t mbar[2 * NST];   // full[0..2], empty[3..5]
    __shared__ float s_v1[BM][4], s_v2[BM][4];
    __shared__ int   s_i1[BM][4], s_i2[BM][4];
    __shared__ int   s_bmu[BM];

    const int tid = threadIdx.x;
    const int wid = tid >> 5;
    const int lane = tid & 31;
    const int g4 = lane >> 2;
    const int tig = lane & 3;
    const int warpM = wid & 1;        // 2 M-warps, 32 rows each
    const int warpN = wid >> 1;       // 4 N-warps, 32 cols each
    const int rowBase = blockIdx.x * BM;
    const uint32_t sb = smem_u32(dynsmem);
    const uint32_t mb = smem_u32(mbar);

    // ldmatrix lane decomposition (proven mapping R7-R11)
    const int lr = lane & 15;
    const int lh = lane >> 4;
    const int bt = lane >> 3;
    const int br = lane & 7;
    const int b_noff = ((bt >> 1) << 3) + br;
    const int b_koff = (bt & 1) << 4;

    // consumer per-warp smem offsets (stage-relative, hoisted)
    const uint32_t aoff_h = STG_AH + (uint32_t)((warpM * 32 + lr) * SROW + lh * 16);
    const uint32_t aoff_l = STG_AL + (uint32_t)((warpM * 32 + lr) * SROW + lh * 16);
    const uint32_t boff_h = STG_BH + (uint32_t)((warpN * 32 + b_noff) * SROW + b_koff);
    const uint32_t boff_l = STG_BL + (uint32_t)((warpN * 32 + b_noff) * SROW + b_koff);

    // producer mapping: 6 cp16/thread/stage, incremental global pointers
    const int bR = tid >> 1;              // B row 0..127
    const int bQ = (tid & 1) * 2;         // B quarters bQ, bQ+1
    const int aR = tid >> 2;              // A row 0..63
    const int aQ = tid & 3;               // A quarter
    const uint32_t bOff = (uint32_t)(bR * SROW + bQ * 16);
    const uint32_t aOff = (uint32_t)(aR * SROW + aQ * 16);
    const __half* pwh = g_wh + (size_t)bR * DDIM + bQ * 8;
    const __half* pwl = g_wl + (size_t)bR * DDIM + bQ * 8;
    const __half* pxh = g_xh + (size_t)(rowBase + aR) * DDIM + aQ * 8;
    const __half* pxl = g_xl + (size_t)(rowBase + aR) * DDIM + aQ * 8;

    if (tid == 0) {
#pragma unroll
        for (int s = 0; s < NST; ++s) {
            MBAR_INIT(mb + s * 8, NTH);             // full: 256 cp-arrivals
            MBAR_INIT(mb + (NST + s) * 8, 8);       // empty: 8 warp-arrivals
        }
    }
    __syncthreads();   // barriers visible before any arrival

    // prologue: fill stages 0,1 (producer steps 0,1 of chunk 0)
#pragma unroll
    for (int p = 0; p < NST - 1; ++p) {
        const uint32_t stg = sb + p * STG_BYTES;
        cp16(stg + STG_BH + bOff,      pwh);
        cp16(stg + STG_BH + bOff + 16, pwh + 8);
        cp16(stg + STG_BL + bOff,      pwl);
        cp16(stg + STG_BL + bOff + 16, pwl + 8);
        cp16(stg + STG_AH + aOff,      pxh);
        cp16(stg + STG_AL + aOff,      pxl);
        CPASYNC_MBAR_ARRIVE(mb + p * 8);
        pwh += 32; pwl += 32; pxh += 32; pxl += 32;
    }

    // running top-2 per owned sub-row
    float rv1[2][2], rv2[2][2];
    int   ri1[2][2], ri2[2][2];
#pragma unroll
    for (int a = 0; a < 2; ++a)
#pragma unroll
        for (int b = 0; b < 2; ++b) {
            rv1[a][b] = 3.4e38f; rv2[a][b] = 3.4e38f;
            ri1[a][b] = 0x7fffffff; ri2[a][b] = 0x7fffffff;
        }

    // incremental mod-3 stage/phase state (identical protocol to R11)
    int cst = 0, cph = 0;         // consumer (stage, phase)
    int pst = 2, pph = 0;         // producer (stage, phase-of-cycle)
    int gn = NST - 1;             // next producer step
    int pc = NST - 1;             // producer step within its chunk (0..15)

    for (int ch = 0; ch < NCHUNK; ++ch) {
        float2 w2r[4];
#pragma unroll
        for (int nt = 0; nt < 4; ++nt)
            w2r[nt] = *reinterpret_cast<const float2*>(
                &g_w2[ch * BN + warpN * 32 + nt * 8 + tig * 2]);

        float acc[2][4][4];
#pragma unroll
        for (int mt = 0; mt < 2; ++mt)
#pragma unroll
            for (int nt = 0; nt < 4; ++nt)
#pragma unroll
                for (int i = 0; i < 4; ++i) acc[mt][nt][i] = 0.f;

        for (int s = 0; s < NSTEP; ++s) {
            // ---- consumer: wait stage full ----
            MBAR_WAIT_PARITY(mb + cst * 8, cph);
            const uint32_t stg32 = sb + cst * STG_BYTES;

            // two k16 sub-rounds over this BK=32 stage
#pragma unroll
            for (int sub = 0; sub < 2; ++sub) {
                const int so = sub * 32;
                uint32_t ah[2][4], al[2][4], bh[4][2], bl[4][2];

                ldm_x4(ah[0], stg32 + aoff_h + so);
                ldm_x4(ah[1], stg32 + aoff_h + so + 16 * SROW);
                ldm_x4(al[0], stg32 + aoff_l + so);
                ldm_x4(al[1], stg32 + aoff_l + so + 16 * SROW);
                ldm_x4(&bh[0][0], stg32 + boff_h + so);
                ldm_x4(&bh[2][0], stg32 + boff_h + so + 16 * SROW);
                ldm_x4(&bl[0][0], stg32 + boff_l + so);
                ldm_x4(&bl[2][0], stg32 + boff_l + so + 16 * SROW);

#pragma unroll
                for (int mt = 0; mt < 2; ++mt)
#pragma unroll
                    for (int nt = 0; nt < 4; ++nt)
                        mma16816(acc[mt][nt], ah[mt], bh[nt]);   // hi*hi
#pragma unroll
                for (int mt = 0; mt < 2; ++mt)
#pragma unroll
                    for (int nt = 0; nt < 4; ++nt)
                        mma16816(acc[mt][nt], ah[mt], bl[nt]);   // hi*lo
#pragma unroll
                for (int mt = 0; mt < 2; ++mt)
#pragma unroll
                    for (int nt = 0; nt < 4; ++nt)
                        mma16816(acc[mt][nt], al[mt], bh[nt]);   // lo*hi
            }

            // warp done with this stage (sync point sits AFTER MMA issue)
            if (lane == 0) MBAR_ARRIVE(mb + (NST + cst) * 8);
            if (++cst == NST) { cst = 0; cph ^= 1; }

            // ---- producer: fill stage for step gn ----
            if (gn < TOTSTEP) {
                if (gn >= NST)   // wait consumers of previous cycle
                    MBAR_WAIT_PARITY(mb + (NST + pst) * 8, pph ^ 1);
                const uint32_t stg = sb + pst * STG_BYTES;
                cp16(stg + STG_BH + bOff,      pwh);
                cp16(stg + STG_BH + bOff + 16, pwh + 8);
                cp16(stg + STG_BL + bOff,      pwl);
                cp16(stg + STG_BL + bOff + 16, pwl + 8);
                cp16(stg + STG_AH + aOff,      pxh);
                cp16(stg + STG_AL + aOff,      pxl);
                CPASYNC_MBAR_ARRIVE(mb + pst * 8);
                pwh += 32; pwl += 32; pxh += 32; pxl += 32;
                if (++pc == NSTEP) {            // producer crosses chunk boundary
                    pc = 0;
                    pwh += (size_t)(BN - 1) * DDIM;
                    pwl += (size_t)(BN - 1) * DDIM;
                    pxh -= DDIM;
                    pxl -= DDIM;
                }
                ++gn;
                if (++pst == NST) { pst = 0; pph ^= 1; }
            }
        }

        // epilogue: per-chunk local top-2, butterfly over 4 threads, merge
        const int idxBase = ch * BN + warpN * 32 + tig * 2;
#pragma unroll
        for (int mt = 0; mt < 2; ++mt) {
#pragma unroll
            for (int r2 = 0; r2 < 2; ++r2) {
                float lv1 = 3.4e38f, lv2 = 3.4e38f;
                int li1 = 0x7fffffff, li2 = 0x7fffffff;
#pragma unroll
                for (int nt = 0; nt < 4; ++nt) {
#pragma unroll
                    for (int c2 = 0; c2 < 2; ++c2) {
                        float dot = acc[mt][nt][r2 * 2 + c2];
                        float w2v = c2 ? w2r[nt].y : w2r[nt].x;
                        float dist = fmaf(-2.f, dot, w2v);
                        top2_upd(dist, idxBase + nt * 8 + c2, lv1, li1, lv2, li2);
                    }
                }
#pragma unroll
                for (int off = 1; off < 4; off <<= 1) {
                    float o1 = __shfl_xor_sync(0xffffffffu, lv1, off);
                    int   p1 = __shfl_xor_sync(0xffffffffu, li1, off);
                    float o2 = __shfl_xor_sync(0xffffffffu, lv2, off);
                    int   p2 = __shfl_xor_sync(0xffffffffu, li2, off);
                    top2_upd(o1, p1, lv1, li1, lv2, li2);
                    top2_upd(o2, p2, lv1, li1, lv2, li2);
                }
                top2_upd(lv1, li1, rv1[mt][r2], ri1[mt][r2], rv2[mt][r2], ri2[mt][r2]);
                top2_upd(lv2, li2, rv1[mt][r2], ri1[mt][r2], rv2[mt][r2], ri2[mt][r2]);
            }
        }
    }

    // cross-warp merge + margin test + exact refine
    if (tig == 0) {
#pragma unroll
        for (int mt = 0; mt < 2; ++mt)
#pragma unroll
            for (int r2 = 0; r2 < 2; ++r2) {
                int row = warpM * 32 + mt * 16 + g4 + r2 * 8;
                s_v1[row][warpN] = rv1[mt][r2]; s_i1[row][warpN] = ri1[mt][r2];
                s_v2[row][warpN] = rv2[mt][r2]; s_i2[row][warpN] = ri2[mt][r2];
            }
    }
    __syncthreads();
    if (tid < BM) {
        float v1 = s_v1[tid][0], v2 = s_v2[tid][0];
        int   i1 = s_i1[tid][0], i2 = s_i2[tid][0];
#pragma unroll
        for (int wn = 1; wn < 4; ++wn) {
            top2_upd(s_v1[tid][wn], s_i1[tid][wn], v1, i1, v2, i2);
            top2_upd(s_v2[tid][wn], s_i2[tid][wn], v1, i1, v2, i2);
        }
        int bmu = i1;
        if (v2 - v1 < MARGIN_TH) {
            // exact fp32 refine: identical FMA chain to the validated r1 kernel
            const float* xr = x + (size_t)(rowBase + tid) * DDIM;
            const float* w1p = w + (size_t)i1 * DDIM;
            const float* w2p = w + (size_t)i2 * DDIM;
            float a1 = 0.f, a2 = 0.f;
#pragma unroll 8
            for (int k = 0; k < DDIM; ++k) {
                float xv = xr[k];
                a1 = fmaf(xv, w1p[k], a1);
                a2 = fmaf(xv, w2p[k], a2);
            }
            float d1 = fmaf(-2.f, a1, g_w2[i1]);
            float d2 = fmaf(-2.f, a2, g_w2[i2]);
            if (d2 < d1 || (d2 == d1 && i2 < i1)) bmu = i2;
        }
        s_bmu[tid] = bmu;
    }
    __syncthreads();

    for (int t = tid; t < BM * (DDIM / 4); t += NTH) {
        int r = t >> 7;
        int cc = t & 127;
        reinterpret_cast<float4*>(out + (size_t)(rowBase + r) * DDIM)[cc] =
            reinterpret_cast<const float4*>(w + (size_t)s_bmu[r] * DDIM)[cc];
    }
}

// ---------------- launch ----------------
extern "C" void kernel_launch(void* const* d_in, const int* in_sizes, int n_in,
                              void* d_out, int out_size) {
    const float* x = (const float*)d_in[0];
    const float* w = (const float*)d_in[1];
    float* out = (float*)d_out;

    __half *xh, *xl, *wh, *wl;
    cudaGetSymbolAddress((void**)&xh, g_xh);
    cudaGetSymbolAddress((void**)&xl, g_xl);
    cudaGetSymbolAddress((void**)&wh, g_wh);
    cudaGetSymbolAddress((void**)&wl, g_wl);

    prep16<<<(NPTS * DDIM / 4) / 256, 256>>>(x, xh, xl);
    prep16<<<(KNEU * DDIM / 4) / 256, 256>>>(w, wh, wl);
    w2_kernel<<<KNEU / 8, 256>>>(w);

    cudaFuncSetAttribute(som_mma, cudaFuncAttributeMaxDynamicSharedMemorySize, SMEM_DYN);
    som_mma<<<NPTS / BM, NTH, SMEM_DYN>>>(x, w, out);
}

// round 15
// speedup vs baseline: 1.3812x; 1.0295x over previous
#include <cuda_runtime.h>
#include <cuda_fp16.h>
#include <cstdint>

// KohonenMap: 3xFP16-split mma.sync (hh+hl+lh) top-2 pass + exact fp32 refine.
// R15: R14 + cheap mbarrier waits: poll phase bit63 via ld.acquire (~30cyc)
// instead of mbarrier.try_wait (~90cyc fast path). Self-calibrating: fast path
// enabled only if bit63 provably flips per phase; else falls back to R14 waits.
#define NPTS 65536
#define KNEU 4096
#define DDIM 512
#define BM 64
#define BN 128
#define NTH 256
#define NST 3
#define NCHUNK (KNEU / BN)    // 32
#define NSTEP  (DDIM / 32)    // 16 BK-32 steps per chunk
#define TOTSTEP (NCHUNK * NSTEP)   // 512
#define MARGIN_TH 0.05f

__device__ __half g_xh[(size_t)NPTS * DDIM];
__device__ __half g_xl[(size_t)NPTS * DDIM];
__device__ __half g_wh[(size_t)KNEU * DDIM];
__device__ __half g_wl[(size_t)KNEU * DDIM];
__device__ float  g_w2[KNEU];

// stage (BK=32, 80B-padded rows; 64B data per row):
//   Ah[64x80] Al[64x80] Bh[128x80] Bl[128x80] = 30720 B
#define SROW 80
#define STG_AH 0
#define STG_AL 5120
#define STG_BH 10240
#define STG_BL 20480
#define STG_BYTES 30720
#define SMEM_DYN (NST * STG_BYTES)   // 92160 -> 2 CTAs/SM

extern __shared__ char dynsmem[];

__device__ __forceinline__ uint32_t smem_u32(const void* p) {
    uint32_t a;
    asm("{ .reg .u64 t; cvta.to.shared.u64 t, %1; cvt.u32.u64 %0, t; }" : "=r"(a) : "l"(p));
    return a;
}
__device__ __forceinline__ void cp16(uint32_t dst, const void* src) {
    asm volatile("cp.async.cg.shared.global [%0], [%1], 16;" :: "r"(dst), "l"(src));
}

#define MBAR_INIT(mb, c) \
    asm volatile("mbarrier.init.shared.b64 [%0], %1;" :: "r"(mb), "r"(c) : "memory")
#define MBAR_ARRIVE(mb) \
    asm volatile("mbarrier.arrive.shared.b64 _, [%0];" :: "r"(mb) : "memory")
#define CPASYNC_MBAR_ARRIVE(mb) \
    asm volatile("cp.async.mbarrier.arrive.noinc.shared.b64 [%0];" :: "r"(mb) : "memory")

// acquire-load of the mbarrier word (phase bit lives at bit63 on sm_10x)
__device__ __forceinline__ uint64_t mbar_peek(uint32_t mb_) {
    uint64_t v;
    asm volatile("ld.acquire.cta.shared::cta.b64 %0, [%1];" : "=l"(v) : "r"(mb_) : "memory");
    return v;
}

// HW-sleep wait (proven R14 path)
#define MBAR_WAIT_SLOW(mbar_addr, par) do {                                              \
    uint32_t _mb = (uint32_t)(mbar_addr); uint32_t _p = (uint32_t)(par); uint32_t _done; \
    asm volatile("{ .reg .pred p; mbarrier.try_wait.parity.acquire.cta.shared::cta.b64 " \
                 "p, [%1], %2; selp.b32 %0,1,0,p; }"                                     \
                 : "=r"(_done) : "r"(_mb), "r"(_p) : "memory");                          \
    if (!_done) {                                                                        \
        asm volatile("{ .reg .pred P1; WL_%=: "                                          \
            "mbarrier.try_wait.parity.acquire.cta.shared::cta.b64 P1, [%0], %1, 0x989680;"\
            " @P1 bra.uni WD_%=; bra.uni WL_%=; WD_%=: }"                                \
            :: "r"(_mb), "r"(_p) : "memory");                                            \
    }                                                                                    \
} while (0)

// fast wait: one ld.acquire peek; if completed-signature matches, proceed;
// otherwise HW-sleep. pflag==0 -> always slow path (exactly R14 behavior).
#define MBAR_WAIT(mbar_addr, par) do {                                                   \
    uint32_t _mbf = (uint32_t)(mbar_addr); uint32_t _pf = (uint32_t)(par);               \
    uint64_t _vf = mbar_peek(_mbf);                                                      \
    if (!(pflag && ((uint32_t)(_vf >> 63) == (psdone ^ _pf))))                           \
        MBAR_WAIT_SLOW(_mbf, _pf);                                                       \
} while (0)

__device__ __forceinline__ void ldm_x4(uint32_t* r, uint32_t addr) {
    asm volatile("ldmatrix.sync.aligned.m8n8.x4.shared.b16 {%0,%1,%2,%3}, [%4];"
        : "=r"(r[0]), "=r"(r[1]), "=r"(r[2]), "=r"(r[3]) : "r"(addr));
}

__device__ __forceinline__ void mma16816(float* c, const uint32_t* a, const uint32_t* b) {
    asm volatile(
        "mma.sync.aligned.m16n8k16.row.col.f32.f16.f16.f32 "
        "{%0,%1,%2,%3}, {%4,%5,%6,%7}, {%8,%9}, {%0,%1,%2,%3};"
        : "+f"(c[0]), "+f"(c[1]), "+f"(c[2]), "+f"(c[3])
        : "r"(a[0]), "r"(a[1]), "r"(a[2]), "r"(a[3]), "r"(b[0]), "r"(b[1]));
}

__device__ __forceinline__ void top2_upd(float d, int idx, float& v1, int& i1,
                                         float& v2, int& i2) {
    if (d < v1 || (d == v1 && idx < i1)) { v2 = v1; i2 = i1; v1 = d; i1 = idx; }
    else if (d < v2 || (d == v2 && idx < i2)) { v2 = d; i2 = idx; }
}

// ---------------- prep kernels ----------------
__global__ void prep16(const float* __restrict__ s, __half* __restrict__ dh,
                       __half* __restrict__ dl) {
    size_t i = (size_t)blockIdx.x * blockDim.x + threadIdx.x;
    float4 v = reinterpret_cast<const float4*>(s)[i];
    __half hx = __float2half_rn(v.x), hy = __float2half_rn(v.y);
    __half hz = __float2half_rn(v.z), hw = __float2half_rn(v.w);
    __half lx = __float2half_rn(v.x - __half2float(hx));
    __half ly = __float2half_rn(v.y - __half2float(hy));
    __half lz = __float2half_rn(v.z - __half2float(hz));
    __half lw = __float2half_rn(v.w - __half2float(hw));
    __half2 h01 = __halves2half2(hx, hy), h23 = __halves2half2(hz, hw);
    __half2 l01 = __halves2half2(lx, ly), l23 = __halves2half2(lz, lw);
    uint2 ph, pl;
    ph.x = *reinterpret_cast<uint32_t*>(&h01); ph.y = *reinterpret_cast<uint32_t*>(&h23);
    pl.x = *reinterpret_cast<uint32_t*>(&l01); pl.y = *reinterpret_cast<uint32_t*>(&l23);
    reinterpret_cast<uint2*>(dh)[i] = ph;
    reinterpret_cast<uint2*>(dl)[i] = pl;
}

__global__ void w2_kernel(const float* __restrict__ w) {
    int warp = (blockIdx.x * blockDim.x + threadIdx.x) >> 5;
    int lane = threadIdx.x & 31;
    if (warp >= KNEU) return;
    const float4* row = reinterpret_cast<const float4*>(w + (size_t)warp * DDIM);
    float s = 0.f;
#pragma unroll
    for (int i = 0; i < DDIM / 128; ++i) {
        float4 v = row[lane + i * 32];
        s += v.x * v.x + v.y * v.y + v.z * v.z + v.w * v.w;
    }
#pragma unroll
    for (int off = 16; off > 0; off >>= 1) s += __shfl_xor_sync(0xffffffff, s, off);
    if (lane == 0) g_w2[warp] = s;
}

// ---------------- main kernel ----------------
__global__ void __launch_bounds__(NTH, 2)
som_mma(const float* __restrict__ x, const float* __restrict__ w,
        float* __restrict__ out) {
    __shared__ __align__(8) uint64_t mbar[2 * NST];   // full[0..2], empty[3..5]
    __shared__ float s_v1[BM][4], s_v2[BM][4];
    __shared__ int   s_i1[BM][4], s_i2[BM][4];
    __shared__ int   s_bmu[BM];

    const int tid = threadIdx.x;
    const int wid = tid >> 5;
    const int lane = tid & 31;
    const int g4 = lane >> 2;
    const int tig = lane & 3;
    const int warpM = wid & 1;        // 2 M-warps, 32 rows each
    const int warpN = wid >> 1;       // 4 N-warps, 32 cols each
    const int rowBase = blockIdx.x * BM;
    const uint32_t sb = smem_u32(dynsmem);
    const uint32_t mb = smem_u32(mbar);

    // ldmatrix lane decomposition (proven mapping R7-R14)
    const int lr = lane & 15;
    const int lh = lane >> 4;
    const int bt = lane >> 3;
    const int br = lane & 7;
    const int b_noff = ((bt >> 1) << 3) + br;
    const int b_koff = (bt & 1) << 4;

    // consumer per-warp smem offsets (stage-relative, hoisted)
    const uint32_t aoff_h = STG_AH + (uint32_t)((warpM * 32 + lr) * SROW + lh * 16);
    const uint32_t aoff_l = STG_AL + (uint32_t)((warpM * 32 + lr) * SROW + lh * 16);
    const uint32_t boff_h = STG_BH + (uint32_t)((warpN * 32 + b_noff) * SROW + b_koff);
    const uint32_t boff_l = STG_BL + (uint32_t)((warpN * 32 + b_noff) * SROW + b_koff);

    // producer mapping: 6 cp16/thread/stage, incremental global pointers
    const int bR = tid >> 1;              // B row 0..127
    const int bQ = (tid & 1) * 2;         // B quarters bQ, bQ+1
    const int aR = tid >> 2;              // A row 0..63
    const int aQ = tid & 3;               // A quarter
    const uint32_t bOff = (uint32_t)(bR * SROW + bQ * 16);
    const uint32_t aOff = (uint32_t)(aR * SROW + aQ * 16);
    const __half* pwh = g_wh + (size_t)bR * DDIM + bQ * 8;
    const __half* pwl = g_wl + (size_t)bR * DDIM + bQ * 8;
    const __half* pxh = g_xh + (size_t)(rowBase + aR) * DDIM + aQ * 8;
    const __half* pxl = g_xl + (size_t)(rowBase + aR) * DDIM + aQ * 8;

    if (tid == 0) {
#pragma unroll
        for (int s = 0; s < NST; ++s) {
            MBAR_INIT(mb + s * 8, NTH);             // full: 256 cp-arrivals
            MBAR_INIT(mb + (NST + s) * 8, 8);       // empty: 8 warp-arrivals
        }
    }
    __syncthreads();   // barriers visible before any arrival

    // phase-bit calibration step 1: snapshot bit63 at init (before any arrival)
    const uint32_t b0 = (uint32_t)(mbar_peek(mb) >> 63);
    __syncthreads();   // all snapshots taken before prologue cp arrivals

    // prologue: fill stages 0,1 (producer steps 0,1 of chunk 0)
#pragma unroll
    for (int p = 0; p < NST - 1; ++p) {
        const uint32_t stg = sb + p * STG_BYTES;
        cp16(stg + STG_BH + bOff,      pwh);
        cp16(stg + STG_BH + bOff + 16, pwh + 8);
        cp16(stg + STG_BL + bOff,      pwl);
        cp16(stg + STG_BL + bOff + 16, pwl + 8);
        cp16(stg + STG_AH + aOff,      pxh);
        cp16(stg + STG_AL + aOff,      pxl);
        CPASYNC_MBAR_ARRIVE(mb + p * 8);
        pwh += 32; pwl += 32; pxh += 32; pxl += 32;
    }

    // phase-bit calibration step 2: slow-wait stage0 full (phase 0), then check
    // whether bit63 flipped. pflag=0 disables the fast path entirely (R14 mode).
    MBAR_WAIT_SLOW(mb, 0);
    const uint32_t psdone = (uint32_t)(mbar_peek(mb) >> 63);
    const uint32_t pflag = (psdone != b0) ? 1u : 0u;

    // running top-2 per owned sub-row
    float rv1[2][2], rv2[2][2];
    int   ri1[2][2], ri2[2][2];
#pragma unroll
    for (int a = 0; a < 2; ++a)
#pragma unroll
        for (int b = 0; b < 2; ++b) {
            rv1[a][b] = 3.4e38f; rv2[a][b] = 3.4e38f;
            ri1[a][b] = 0x7fffffff; ri2[a][b] = 0x7fffffff;
        }

    // incremental mod-3 stage/phase state (identical protocol to R11/R14)
    int cst = 0, cph = 0;         // consumer (stage, phase)
    int pst = 2, pph = 0;         // producer (stage, phase-of-cycle)
    int gn = NST - 1;             // next producer step
    int pc = NST - 1;             // producer step within its chunk (0..15)

    for (int ch = 0; ch < NCHUNK; ++ch) {
        float2 w2r[4];
#pragma unroll
        for (int nt = 0; nt < 4; ++nt)
            w2r[nt] = *reinterpret_cast<const float2*>(
                &g_w2[ch * BN + warpN * 32 + nt * 8 + tig * 2]);

        float acc[2][4][4];
#pragma unroll
        for (int mt = 0; mt < 2; ++mt)
#pragma unroll
            for (int nt = 0; nt < 4; ++nt)
#pragma unroll
                for (int i = 0; i < 4; ++i) acc[mt][nt][i] = 0.f;

        for (int s = 0; s < NSTEP; ++s) {
            // ---- consumer: wait stage full (fast peek, slow fallback) ----
            MBAR_WAIT(mb + cst * 8, cph);
            const uint32_t stg32 = sb + cst * STG_BYTES;

            // two k16 sub-rounds over this BK=32 stage
#pragma unroll
            for (int sub = 0; sub < 2; ++sub) {
                const int so = sub * 32;
                uint32_t ah[2][4], al[2][4], bh[4][2], bl[4][2];

                ldm_x4(ah[0], stg32 + aoff_h + so);
                ldm_x4(ah[1], stg32 + aoff_h + so + 16 * SROW);
                ldm_x4(al[0], stg32 + aoff_l + so);
                ldm_x4(al[1], stg32 + aoff_l + so + 16 * SROW);
                ldm_x4(&bh[0][0], stg32 + boff_h + so);
                ldm_x4(&bh[2][0], stg32 + boff_h + so + 16 * SROW);
                ldm_x4(&bl[0][0], stg32 + boff_l + so);
                ldm_x4(&bl[2][0], stg32 + boff_l + so + 16 * SROW);

#pragma unroll
                for (int mt = 0; mt < 2; ++mt)
#pragma unroll
                    for (int nt = 0; nt < 4; ++nt)
                        mma16816(acc[mt][nt], ah[mt], bh[nt]);   // hi*hi
#pragma unroll
                for (int mt = 0; mt < 2; ++mt)
#pragma unroll
                    for (int nt = 0; nt < 4; ++nt)
                        mma16816(acc[mt][nt], ah[mt], bl[nt]);   // hi*lo
#pragma unroll
                for (int mt = 0; mt < 2; ++mt)
#pragma unroll
                    for (int nt = 0; nt < 4; ++nt)
                        mma16816(acc[mt][nt], al[mt], bh[nt]);   // lo*hi
            }

            // warp done with this stage (sync point sits AFTER MMA issue)
            if (lane == 0) MBAR_ARRIVE(mb + (NST + cst) * 8);
            if (++cst == NST) { cst = 0; cph ^= 1; }

            // ---- producer: fill stage for step gn ----
            if (gn < TOTSTEP) {
                if (gn >= NST)   // wait consumers of previous cycle
                    MBAR_WAIT(mb + (NST + pst) * 8, pph ^ 1);
                const uint32_t stg = sb + pst * STG_BYTES;
                cp16(stg + STG_BH + bOff,      pwh);
                cp16(stg + STG_BH + bOff + 16, pwh + 8);
                cp16(stg + STG_BL + bOff,      pwl);
                cp16(stg + STG_BL + bOff + 16, pwl + 8);
                cp16(stg + STG_AH + aOff,      pxh);
                cp16(stg + STG_AL + aOff,      pxl);
                CPASYNC_MBAR_ARRIVE(mb + pst * 8);
                pwh += 32; pwl += 32; pxh += 32; pxl += 32;
                if (++pc == NSTEP) {            // producer crosses chunk boundary
                    pc = 0;
                    pwh += (size_t)(BN - 1) * DDIM;
                    pwl += (size_t)(BN - 1) * DDIM;
                    pxh -= DDIM;
                    pxl -= DDIM;
                }
                ++gn;
                if (++pst == NST) { pst = 0; pph ^= 1; }
            }
        }

        // epilogue: per-chunk local top-2, butterfly over 4 threads, merge
        const int idxBase = ch * BN + warpN * 32 + tig * 2;
#pragma unroll
        for (int mt = 0; mt < 2; ++mt) {
#pragma unroll
            for (int r2 = 0; r2 < 2; ++r2) {
                float lv1 = 3.4e38f, lv2 = 3.4e38f;
                int li1 = 0x7fffffff, li2 = 0x7fffffff;
#pragma unroll
                for (int nt = 0; nt < 4; ++nt) {
#pragma unroll
                    for (int c2 = 0; c2 < 2; ++c2) {
                        float dot = acc[mt][nt][r2 * 2 + c2];
                        float w2v = c2 ? w2r[nt].y : w2r[nt].x;
                        float dist = fmaf(-2.f, dot, w2v);
                        top2_upd(dist, idxBase + nt * 8 + c2, lv1, li1, lv2, li2);
                    }
                }
#pragma unroll
                for (int off = 1; off < 4; off <<= 1) {
                    float o1 = __shfl_xor_sync(0xffffffffu, lv1, off);
                    int   p1 = __shfl_xor_sync(0xffffffffu, li1, off);
                    float o2 = __shfl_xor_sync(0xffffffffu, lv2, off);
                    int   p2 = __shfl_xor_sync(0xffffffffu, li2, off);
                    top2_upd(o1, p1, lv1, li1, lv2, li2);
                    top2_upd(o2, p2, lv1, li1, lv2, li2);
                }
                top2_upd(lv1, li1, rv1[mt][r2], ri1[mt][r2], rv2[mt][r2], ri2[mt][r2]);
                top2_upd(lv2, li2, rv1[mt][r2], ri1[mt][r2], rv2[mt][r2], ri2[mt][r2]);
            }
        }
    }

    // cross-warp merge + margin test + exact refine
    if (tig == 0) {
#pragma unroll
        for (int mt = 0; mt < 2; ++mt)
#pragma unroll
            for (int r2 = 0; r2 < 2; ++r2) {
                int row = warpM * 32 + mt * 16 + g4 + r2 * 8;
                s_v1[row][warpN] = rv1[mt][r2]; s_i1[row][warpN] = ri1[mt][r2];
                s_v2[row][warpN] = rv2[mt][r2]; s_i2[row][warpN] = ri2[mt][r2];
            }
    }
    __syncthreads();
    if (tid < BM) {
        float v1 = s_v1[tid][0], v2 = s_v2[tid][0];
        int   i1 = s_i1[tid][0], i2 = s_i2[tid][0];
#pragma unroll
        for (int wn = 1; wn < 4; ++wn) {
            top2_upd(s_v1[tid][wn], s_i1[tid][wn], v1, i1, v2, i2);
            top2_upd(s_v2[tid][wn], s_i2[tid][wn], v1, i1, v2, i2);
        }
        int bmu = i1;
        if (v2 - v1 < MARGIN_TH) {
            // exact fp32 refine: identical FMA chain to the validated r1 kernel
            const float* xr = x + (size_t)(rowBase + tid) * DDIM;
            const float* w1p = w + (size_t)i1 * DDIM;
            const float* w2p = w + (size_t)i2 * DDIM;
            float a1 = 0.f, a2 = 0.f;
#pragma unroll 8
            for (int k = 0; k < DDIM; ++k) {
                float xv = xr[k];
                a1 = fmaf(xv, w1p[k], a1);
                a2 = fmaf(xv, w2p[k], a2);
            }
            float d1 = fmaf(-2.f, a1, g_w2[i1]);
            float d2 = fmaf(-2.f, a2, g_w2[i2]);
            if (d2 < d1 || (d2 == d1 && i2 < i1)) bmu = i2;
        }
        s_bmu[tid] = bmu;
    }
    __syncthreads();

    for (int t = tid; t < BM * (DDIM / 4); t += NTH) {
        int r = t >> 7;
        int cc = t & 127;
        reinterpret_cast<float4*>(out + (size_t)(rowBase + r) * DDIM)[cc] =
            reinterpret_cast<const float4*>(w + (size_t)s_bmu[r] * DDIM)[cc];
    }
}

// ---------------- launch ----------------
extern "C" void kernel_launch(void* const* d_in, const int* in_sizes, int n_in,
                              void* d_out, int out_size) {
    const float* x = (const float*)d_in[0];
    const float* w = (const float*)d_in[1];
    float* out = (float*)d_out;

    __half *xh, *xl, *wh, *wl;
    cudaGetSymbolAddress((void**)&xh, g_xh);
    cudaGetSymbolAddress((void**)&xl, g_xl);
    cudaGetSymbolAddress((void**)&wh, g_wh);
    cudaGetSymbolAddress((void**)&wl, g_wl);

    prep16<<<(NPTS * DDIM / 4) / 256, 256>>>(x, xh, xl);
    prep16<<<(KNEU * DDIM / 4) / 256, 256>>>(w, wh, wl);
    w2_kernel<<<KNEU / 8, 256>>>(w);

    cudaFuncSetAttribute(som_mma, cudaFuncAttributeMaxDynamicSharedMemorySize, SMEM_DYN);
    som_mma<<<NPTS / BM, NTH, SMEM_DYN>>>(x, w, out);
}